// round 14
// baseline (speedup 1.0000x reference)
#include <cuda_runtime.h>
#include <cuda_bf16.h>
#include <math.h>
#include <stdint.h>
#include <string.h>

#define EDGES    800000
#define NNODES   50000
#define HDIM     128
#define K1       384
#define FFDIM    512
#define TEM      128
#define NTILES   (EDGES / TEM)
#define GRID_E   148
#define TNN      128
#define NTH      512
#define SCALE_F  30.0f
#define LN_EPS   1e-5f

#define SA2 272

// edge smem layout (bytes)
#define EW1B_OFF 0
#define EW2_OFF  (128 * SA2)                 // 34816
#define EW3_OFF  (2 * 128 * SA2)             // 69632
#define EPS_OFF  (3 * 128 * SA2)             // 104448: PS fp32 128x132 (67584 B)
#define EX3_OFF  EPS_OFF                     // X3 reuses PS region (34816 <= 67584)
#define EX_OFF   (EPS_OFF + 128 * 132 * 4)   // 172032: XB (hE -> X2)
#define EDGE_SMEM (EX_OFF + 128 * SA2)       // 206848

// precompute kernel smem layout
#define PWA_OFF  0
#define PWC_OFF  (128 * SA2)
#define PX_OFF   (2 * 128 * SA2)
#define PST_OFF  (3 * 128 * SA2)
#define PRE_SMEM (PST_OFF + 128 * 132 * 4)

// node kernel smem layout
#define HS_STRIDE 132
#define HS_BYTES  (TNN * HS_STRIDE * 4)
#define NX_OFF    HS_BYTES
#define NH_OFF    (NX_OFF + 128 * SA2)
#define NW_OFF    (NH_OFF + 128 * SA2)
#define NODE_SMEM (NW_OFF + 128 * SA2)

__device__ float g_nsum[(size_t)NNODES * HDIM];
__device__ float g_cnt[NNODES];
__device__ float g_pre_s[(size_t)NNODES * HDIM];
__device__ float g_pre_d[(size_t)NNODES * HDIM];

__device__ __forceinline__ float gelu_exact(float x) {
    return 0.5f * x * (1.0f + erff(x * 0.70710678118654752440f));
}
__device__ __forceinline__ uint32_t smem_u32(const void* p) {
    uint32_t a;
    asm("{ .reg .u64 t; cvta.to.shared.u64 t, %1; cvt.u32.u64 %0, t; }" : "=r"(a) : "l"(p));
    return a;
}
__device__ __forceinline__ void ldsm4(uint32_t r[4], uint32_t addr) {
    asm volatile("ldmatrix.sync.aligned.m8n8.x4.shared.b16 {%0,%1,%2,%3}, [%4];"
                 : "=r"(r[0]), "=r"(r[1]), "=r"(r[2]), "=r"(r[3]) : "r"(addr));
}
__device__ __forceinline__ void mma_bf16(float c[4], const uint32_t a[4],
                                         uint32_t b0, uint32_t b1) {
    asm volatile("mma.sync.aligned.m16n8k16.row.col.f32.bf16.bf16.f32 "
                 "{%0,%1,%2,%3}, {%4,%5,%6,%7}, {%8,%9}, {%0,%1,%2,%3};"
                 : "+f"(c[0]), "+f"(c[1]), "+f"(c[2]), "+f"(c[3])
                 : "r"(a[0]), "r"(a[1]), "r"(a[2]), "r"(a[3]), "r"(b0), "r"(b1));
}
__device__ __forceinline__ void st_bf16x4(char* dst, float4 v) {
    __nv_bfloat162 h0 = __floats2bfloat162_rn(v.x, v.y);
    __nv_bfloat162 h1 = __floats2bfloat162_rn(v.z, v.w);
    uint32_t u0, u1;
    memcpy(&u0, &h0, 4); memcpy(&u1, &h1, 4);
    *(uint2*)dst = make_uint2(u0, u1);
}

// generic warp tile: M = 32 (2 x m16), N = NP*16
template <int KTOT, int SA, int SW, int NP>
__device__ __forceinline__ void mma_tile(const char* A, const char* W,
                                         float (&acc)[2][2 * NP][4],
                                         int wm, int wn, int lane) {
    int row_off = (lane & 7) + ((lane >> 3) & 1) * 8;
    int col_off = (lane >> 4) * 8;
#pragma unroll
    for (int k0 = 0; k0 < KTOT; k0 += 16) {
        uint32_t a[2][4];
#pragma unroll
        for (int mi = 0; mi < 2; mi++)
            ldsm4(a[mi], smem_u32(A + (wm * 32 + mi * 16 + row_off) * SA
                                     + (k0 + col_off) * 2));
        uint32_t b[NP][4];
#pragma unroll
        for (int np = 0; np < NP; np++)
            ldsm4(b[np], smem_u32(W + (wn * 16 * NP + np * 16 + row_off) * SW
                                     + (k0 + col_off) * 2));
#pragma unroll
        for (int mi = 0; mi < 2; mi++)
#pragma unroll
            for (int np = 0; np < NP; np++) {
                mma_bf16(acc[mi][2 * np],     a[mi], b[np][0], b[np][2]);
                mma_bf16(acc[mi][2 * np + 1], a[mi], b[np][1], b[np][3]);
            }
    }
}
template <int NP>
__device__ __forceinline__ void init_bias(float (&acc)[2][2 * NP][4],
                                          const float* sb, int wn, int q) {
#pragma unroll
    for (int ni = 0; ni < 2 * NP; ni++) {
        int c = wn * 16 * NP + ni * 8 + q * 2;
        float v0 = sb[c], v1 = sb[c + 1];
#pragma unroll
        for (int mi = 0; mi < 2; mi++) {
            acc[mi][ni][0] = v0; acc[mi][ni][1] = v1;
            acc[mi][ni][2] = v0; acc[mi][ni][3] = v1;
        }
    }
}
template <int NP>
__device__ __forceinline__ void epi_gelu(char* X, float (&acc)[2][2 * NP][4],
                                         int wm, int wn, int g, int q) {
#pragma unroll
    for (int mi = 0; mi < 2; mi++) {
        int r0 = wm * 32 + mi * 16 + g;
#pragma unroll
        for (int ni = 0; ni < 2 * NP; ni++) {
            int c = wn * 16 * NP + ni * 8 + q * 2;
            __nv_bfloat162 h0 = __floats2bfloat162_rn(gelu_exact(acc[mi][ni][0]),
                                                      gelu_exact(acc[mi][ni][1]));
            __nv_bfloat162 h1 = __floats2bfloat162_rn(gelu_exact(acc[mi][ni][2]),
                                                      gelu_exact(acc[mi][ni][3]));
            uint32_t u0, u1;
            memcpy(&u0, &h0, 4); memcpy(&u1, &h1, 4);
            *(uint32_t*)(X + r0 * SA2 + c * 2) = u0;
            *(uint32_t*)(X + (r0 + 8) * SA2 + c * 2) = u1;
        }
    }
}
template <int NP>
__device__ __forceinline__ void frag_to_f32(float* ST, float (&acc)[2][2 * NP][4],
                                            int wm, int wn, int g, int q) {
#pragma unroll
    for (int mi = 0; mi < 2; mi++) {
        int r0 = wm * 32 + mi * 16 + g;
#pragma unroll
        for (int ni = 0; ni < 2 * NP; ni++) {
            int c = wn * 16 * NP + ni * 8 + q * 2;
            *(float2*)(ST + r0 * 132 + c)       = make_float2(acc[mi][ni][0], acc[mi][ni][1]);
            *(float2*)(ST + (r0 + 8) * 132 + c) = make_float2(acc[mi][ni][2], acc[mi][ni][3]);
        }
    }
}

// ============================================================================
// Precompute kernel: pre_s = hV @ W1a^T + b1 ; pre_d = hV @ W1c^T
// ============================================================================
__global__ __launch_bounds__(NTH, 1) void pre_kernel(
    const float* __restrict__ hV, const float* __restrict__ W1,
    const float* __restrict__ b1)
{
    extern __shared__ char smem[];
    char*  Wa = smem + PWA_OFF;
    char*  Wc = smem + PWC_OFF;
    char*  X  = smem + PX_OFF;
    float* ST = (float*)(smem + PST_OFF);

    __shared__ float s_b1[HDIM];

    int tid = threadIdx.x;
    int wid = tid >> 5;
    int lane = tid & 31;
    int wm = wid & 3, wn = wid >> 2;
    int g = lane >> 2, q = lane & 3;
    int n0 = blockIdx.x * TNN;

    if (tid < HDIM) s_b1[tid] = b1[tid];

#pragma unroll 4
    for (int t = 0; t < 8; t++) {
        int idx = tid + t * NTH;
        int n = idx >> 5, c4 = idx & 31;
        st_bf16x4(Wa + n * SA2 + c4 * 8, *(const float4*)(W1 + (size_t)n * K1 + c4 * 4));
        st_bf16x4(Wc + n * SA2 + c4 * 8, *(const float4*)(W1 + (size_t)n * K1 + 256 + c4 * 4));
        int gn = n0 + n;
        float4 v = make_float4(0.f, 0.f, 0.f, 0.f);
        if (gn < NNODES) v = *(const float4*)(hV + (size_t)gn * HDIM + c4 * 4);
        st_bf16x4(X + n * SA2 + c4 * 8, v);
    }
    __syncthreads();

    float acc_s[2][4][4], acc_d[2][4][4];
    init_bias<2>(acc_s, s_b1, wn, q);
    mma_tile<HDIM, SA2, SA2, 2>(X, Wa, acc_s, wm, wn, lane);
#pragma unroll
    for (int mi = 0; mi < 2; mi++)
#pragma unroll
        for (int ni = 0; ni < 4; ni++)
#pragma unroll
            for (int k = 0; k < 4; k++) acc_d[mi][ni][k] = 0.f;
    mma_tile<HDIM, SA2, SA2, 2>(X, Wc, acc_d, wm, wn, lane);

    frag_to_f32<2>(ST, acc_s, wm, wn, g, q);
    __syncthreads();
#pragma unroll 4
    for (int t = 0; t < 32; t++) {
        int idx = tid + t * NTH;
        int n = idx >> 7, o = idx & 127;
        int gn = n0 + n;
        if (gn < NNODES) g_pre_s[(size_t)gn * HDIM + o] = ST[n * 132 + o];
    }
    __syncthreads();
    frag_to_f32<2>(ST, acc_d, wm, wn, g, q);
    __syncthreads();
#pragma unroll 4
    for (int t = 0; t < 32; t++) {
        int idx = tid + t * NTH;
        int n = idx >> 7, o = idx & 127;
        int gn = n0 + n;
        if (gn < NNODES) g_pre_d[(size_t)gn * HDIM + o] = ST[n * 132 + o];
    }
}

// ============================================================================
// Edge kernel: 128-edge tiles, factored layer-1, persistent weights
// ============================================================================
__global__ __launch_bounds__(NTH, 1) void edge_kernel_p(
    const float* __restrict__ hE,
    const int* __restrict__ src, const int* __restrict__ dst,
    const float* __restrict__ W1, const float* __restrict__ b2w,
    const float* __restrict__ W2, const float* __restrict__ W3,
    const float* __restrict__ b3w)
{
    extern __shared__ char smem[];
    char*  W1s = smem + EW1B_OFF;     // W1b = cols 128..255
    char*  W2s = smem + EW2_OFF;
    char*  W3s = smem + EW3_OFF;
    float* PS  = (float*)(smem + EPS_OFF);   // fp32 128x132; X3 reuses this region
    char*  X3  = smem + EX3_OFF;
    char*  XB  = smem + EX_OFF;              // hE bf16 -> X2

    __shared__ int   sidx[2][TEM];
    __shared__ int   didx[2][TEM];
    __shared__ float s_b2[HDIM], s_b3[HDIM];

    int tid = threadIdx.x;
    int wid = tid >> 5;
    int lane = tid & 31;
    int wm = wid & 3, wn = wid >> 2;     // 4M x 4N, NP=2
    int g = lane >> 2, q = lane & 3;

    if (tid < HDIM) { s_b2[tid] = b2w[tid]; s_b3[tid] = b3w[tid]; }
    // persistent weight staging
#pragma unroll 4
    for (int t = 0; t < 8; t++) {
        int idx = tid + t * NTH;
        int n = idx >> 5, c4 = idx & 31;
        st_bf16x4(W1s + n * SA2 + c4 * 8, *(const float4*)(W1 + (size_t)n * K1 + 128 + c4 * 4));
        st_bf16x4(W2s + n * SA2 + c4 * 8, *(const float4*)(W2 + (size_t)n * HDIM + c4 * 4));
        st_bf16x4(W3s + n * SA2 + c4 * 8, *(const float4*)(W3 + (size_t)n * HDIM + c4 * 4));
    }

    // prologue: indices + hE prefetch for first tile
    int tile0 = blockIdx.x;
    float4 he[8];
    {
        size_t e0 = (size_t)tile0 * TEM;
        if (tid < TEM)            sidx[0][tid]       = src[e0 + tid];
        else if (tid < 2 * TEM)   didx[0][tid - TEM] = dst[e0 + (tid - TEM)];
#pragma unroll
        for (int t = 0; t < 8; t++) {
            int idx = tid + t * NTH;
            int e = idx >> 5, c4 = idx & 31;
            he[t] = *(const float4*)(hE + (e0 + e) * HDIM + c4 * 4);
        }
    }
    __syncthreads();

    int p = 0;
    for (int tile = tile0; tile < NTILES; tile += GRID_E, p ^= 1) {
        const int* si = sidx[p];
        const int* di = didx[p];

        // ---- gather: hE from regs; PS = pre_s[src] + pre_d[dst] (L2 loads) ----
#pragma unroll
        for (int t = 0; t < 8; t++) {
            int idx = tid + t * NTH;
            int e = idx >> 5, c4 = idx & 31;
            st_bf16x4(XB + e * SA2 + c4 * 8, he[t]);
            float4 a = *(const float4*)(g_pre_s + (size_t)si[e] * HDIM + c4 * 4);
            float4 b = *(const float4*)(g_pre_d + (size_t)di[e] * HDIM + c4 * 4);
            *(float4*)(PS + e * 132 + c4 * 4) =
                make_float4(a.x + b.x, a.y + b.y, a.z + b.z, a.w + b.w);
        }
        __syncthreads();

        // ---- next tile prefetch (hidden under MMA) ----
        int tnext = tile + GRID_E;
        if (tnext < NTILES) {
            size_t e0n = (size_t)tnext * TEM;
            if (tid < TEM)            sidx[p ^ 1][tid]       = src[e0n + tid];
            else if (tid < 2 * TEM)   didx[p ^ 1][tid - TEM] = dst[e0n + (tid - TEM)];
#pragma unroll
            for (int t = 0; t < 8; t++) {
                int idx = tid + t * NTH;
                int e = idx >> 5, c4 = idx & 31;
                he[t] = *(const float4*)(hE + (e0n + e) * HDIM + c4 * 4);
            }
        }

        float acc[2][4][4];

        // ---- layer 1: acc init from PS, K=128 over hE ----
#pragma unroll
        for (int mi = 0; mi < 2; mi++) {
            int r0 = wm * 32 + mi * 16 + g;
#pragma unroll
            for (int ni = 0; ni < 4; ni++) {
                int c = wn * 32 + ni * 8 + q * 2;
                float2 v0 = *(float2*)(PS + r0 * 132 + c);
                float2 v1 = *(float2*)(PS + (r0 + 8) * 132 + c);
                acc[mi][ni][0] = v0.x; acc[mi][ni][1] = v0.y;
                acc[mi][ni][2] = v1.x; acc[mi][ni][3] = v1.y;
            }
        }
        mma_tile<HDIM, SA2, SA2, 2>(XB, W1s, acc, wm, wn, lane);
        __syncthreads();                       // all warps done reading XB + PS
        epi_gelu<2>(XB, acc, wm, wn, g, q);    // X2 overwrites hE
        __syncthreads();

        // ---- layer 2 ----
        init_bias<2>(acc, s_b2, wn, q);
        mma_tile<HDIM, SA2, SA2, 2>(XB, W2s, acc, wm, wn, lane);
        epi_gelu<2>(X3, acc, wm, wn, g, q);    // X3 in retired PS region
        __syncthreads();

        // ---- layer 3 ----
        init_bias<2>(acc, s_b3, wn, q);
        mma_tile<HDIM, SA2, SA2, 2>(X3, W3s, acc, wm, wn, lane);

        // ---- direct scatter (float2 vector atomics) ----
#pragma unroll
        for (int mi = 0; mi < 2; mi++) {
            int r0 = wm * 32 + mi * 16 + g;
            float* row0 = &g_nsum[(size_t)si[r0] * HDIM];
            float* row1 = &g_nsum[(size_t)si[r0 + 8] * HDIM];
#pragma unroll
            for (int ni = 0; ni < 4; ni++) {
                int c = wn * 32 + ni * 8 + q * 2;
                atomicAdd((float2*)(row0 + c), make_float2(acc[mi][ni][0], acc[mi][ni][1]));
                atomicAdd((float2*)(row1 + c), make_float2(acc[mi][ni][2], acc[mi][ni][3]));
            }
        }
        if (tid < TEM) atomicAdd(&g_cnt[si[tid]], 1.0f);

        __syncthreads();
    }
}

// ============================================================================
// Node kernel (unchanged)
// ============================================================================
__global__ __launch_bounds__(NTH, 1) void node_kernel_mma(
    const float* __restrict__ hV,
    const float* __restrict__ ln1g, const float* __restrict__ ln1b,
    const float* __restrict__ ln2g, const float* __restrict__ ln2b,
    const float* __restrict__ Win,  const float* __restrict__ bin,
    const float* __restrict__ Wout, const float* __restrict__ bout,
    float* __restrict__ out)
{
    extern __shared__ char smem[];
    float* hs = (float*)smem;
    char*  X  = smem + NX_OFF;
    char*  Hb = smem + NH_OFF;
    char*  Wb = smem + NW_OFF;

    __shared__ float s_bout[HDIM];

    int tid = threadIdx.x;
    int wid = tid >> 5;
    int lane = tid & 31;
    int wm = wid & 3, wn = wid >> 2;
    int g = lane >> 2, q = lane & 3;
    int n0 = blockIdx.x * TNN;

    if (tid < HDIM) s_bout[tid] = bout[tid];

#pragma unroll 4
    for (int t = 0; t < 32; t++) {
        int idx = tid + t * NTH;
        int n = idx >> 7, o = idx & 127;
        int gn = n0 + n;
        float v = 0.0f;
        if (gn < NNODES) {
            float c = fmaxf(g_cnt[gn], 1.0f);
            v = hV[(size_t)gn * HDIM + o] + g_nsum[(size_t)gn * HDIM + o] / (c * SCALE_F);
        }
        hs[n * HS_STRIDE + o] = v;
    }
    __syncthreads();

    {
        int n = tid >> 2, q4 = tid & 3;
        float s = 0.0f, ss = 0.0f;
#pragma unroll
        for (int jj = 0; jj < 32; jj++) {
            float v = hs[n * HS_STRIDE + q4 * 32 + jj];
            s += v; ss += v * v;
        }
#pragma unroll
        for (int m = 1; m < 4; m <<= 1) {
            s  += __shfl_xor_sync(0xffffffffu, s,  m);
            ss += __shfl_xor_sync(0xffffffffu, ss, m);
        }
        float mu   = s * (1.0f / 128.0f);
        float var  = ss * (1.0f / 128.0f) - mu * mu;
        float rstd = rsqrtf(var + LN_EPS);
#pragma unroll
        for (int jj = 0; jj < 32; jj += 2) {
            int o = q4 * 32 + jj;
            float v0 = (hs[n * HS_STRIDE + o]     - mu) * rstd * ln1g[o]     + ln1b[o];
            float v1 = (hs[n * HS_STRIDE + o + 1] - mu) * rstd * ln1g[o + 1] + ln1b[o + 1];
            hs[n * HS_STRIDE + o]     = v0;
            hs[n * HS_STRIDE + o + 1] = v1;
            __nv_bfloat162 hh = __floats2bfloat162_rn(v0, v1);
            uint32_t u; memcpy(&u, &hh, 4);
            *(uint32_t*)(X + n * SA2 + o * 2) = u;
        }
    }

    float dh[2][4][4];
    init_bias<2>(dh, s_bout, wn, q);

    for (int nb = 0; nb < 4; nb++) {
        __syncthreads();
#pragma unroll 4
        for (int t = 0; t < 8; t++) {
            int idx = tid + t * NTH;
            int n = idx >> 5, c4 = idx & 31;
            st_bf16x4(Wb + n * SA2 + c4 * 8,
                      *(const float4*)(Win + (size_t)(nb * 128 + n) * HDIM + c4 * 4));
        }
        __syncthreads();

        float acc[2][4][4];
        init_bias<2>(acc, bin + nb * 128, wn, q);
        mma_tile<HDIM, SA2, SA2, 2>(X, Wb, acc, wm, wn, lane);
        __syncthreads();
        epi_gelu<2>(Hb, acc, wm, wn, g, q);

#pragma unroll 4
        for (int t = 0; t < 8; t++) {
            int idx = tid + t * NTH;
            int n = idx >> 5, c4 = idx & 31;
            st_bf16x4(Wb + n * SA2 + c4 * 8,
                      *(const float4*)(Wout + (size_t)n * FFDIM + nb * 128 + c4 * 4));
        }
        __syncthreads();

        mma_tile<HDIM, SA2, SA2, 2>(Hb, Wb, dh, wm, wn, lane);
    }
    __syncthreads();

    float* zs = (float*)X;
#pragma unroll
    for (int mi = 0; mi < 2; mi++) {
        int r0 = wm * 32 + mi * 16 + g;
#pragma unroll
        for (int ni = 0; ni < 4; ni++) {
            int c = wn * 32 + ni * 8 + q * 2;
            zs[r0 * 132 + c]           = dh[mi][ni][0] + hs[r0 * HS_STRIDE + c];
            zs[r0 * 132 + c + 1]       = dh[mi][ni][1] + hs[r0 * HS_STRIDE + c + 1];
            zs[(r0 + 8) * 132 + c]     = dh[mi][ni][2] + hs[(r0 + 8) * HS_STRIDE + c];
            zs[(r0 + 8) * 132 + c + 1] = dh[mi][ni][3] + hs[(r0 + 8) * HS_STRIDE + c + 1];
        }
    }
    __syncthreads();

    {
        int n = tid >> 2, q4 = tid & 3;
        float s = 0.0f, ss = 0.0f;
#pragma unroll
        for (int jj = 0; jj < 32; jj++) {
            float v = zs[n * 132 + q4 * 32 + jj];
            s += v; ss += v * v;
        }
#pragma unroll
        for (int m = 1; m < 4; m <<= 1) {
            s  += __shfl_xor_sync(0xffffffffu, s,  m);
            ss += __shfl_xor_sync(0xffffffffu, ss, m);
        }
        float mu   = s * (1.0f / 128.0f);
        float var  = ss * (1.0f / 128.0f) - mu * mu;
        float rstd = rsqrtf(var + LN_EPS);
        int gn = n0 + n;
        if (gn < NNODES) {
#pragma unroll
            for (int jj = 0; jj < 32; jj++) {
                int o = q4 * 32 + jj;
                float v = zs[n * 132 + o];
                out[(size_t)gn * HDIM + o] = (v - mu) * rstd * ln2g[o] + ln2b[o];
            }
        }
    }
}

// ============================================================================
// Launch
// ============================================================================
extern "C" void kernel_launch(void* const* d_in, const int* in_sizes, int n_in,
                              void* d_out, int out_size)
{
    const float* hV   = (const float*)d_in[0];
    const float* hE   = (const float*)d_in[1];
    const int*   src  = (const int*)  d_in[2];
    const int*   dst  = (const int*)  d_in[4];
    const float* W1   = (const float*)d_in[5];
    const float* b1   = (const float*)d_in[6];
    const float* W2   = (const float*)d_in[7];
    const float* b2   = (const float*)d_in[8];
    const float* W3   = (const float*)d_in[9];
    const float* b3   = (const float*)d_in[10];
    const float* ln1g = (const float*)d_in[11];
    const float* ln1b = (const float*)d_in[12];
    const float* ln2g = (const float*)d_in[13];
    const float* ln2b = (const float*)d_in[14];
    const float* Win  = (const float*)d_in[15];
    const float* bin  = (const float*)d_in[16];
    const float* Wout = (const float*)d_in[17];
    const float* bout = (const float*)d_in[18];
    float* out = (float*)d_out;

    cudaFuncSetAttribute(pre_kernel, cudaFuncAttributeMaxDynamicSharedMemorySize, PRE_SMEM);
    cudaFuncSetAttribute(edge_kernel_p, cudaFuncAttributeMaxDynamicSharedMemorySize, EDGE_SMEM);
    cudaFuncSetAttribute(node_kernel_mma, cudaFuncAttributeMaxDynamicSharedMemorySize, NODE_SMEM);

    void* nsum_p = nullptr;
    void* cnt_p  = nullptr;
    cudaGetSymbolAddress(&nsum_p, g_nsum);
    cudaGetSymbolAddress(&cnt_p,  g_cnt);
    cudaMemsetAsync(nsum_p, 0, sizeof(float) * (size_t)NNODES * HDIM);
    cudaMemsetAsync(cnt_p,  0, sizeof(float) * NNODES);

    int nblk = (NNODES + TNN - 1) / TNN;
    pre_kernel<<<nblk, NTH, PRE_SMEM>>>(hV, W1, b1);
    edge_kernel_p<<<GRID_E, NTH, EDGE_SMEM>>>(hE, src, dst, W1, b2, W2, W3, b3);
    node_kernel_mma<<<nblk, NTH, NODE_SMEM>>>(
        hV, ln1g, ln1b, ln2g, ln2b, Win, bin, Wout, bout, out);
}

// round 15
// speedup vs baseline: 1.6267x; 1.6267x over previous
#include <cuda_runtime.h>
#include <cuda_bf16.h>
#include <math.h>
#include <stdint.h>
#include <string.h>

#define EDGES    800000
#define NNODES   50000
#define HDIM     128
#define K1       384
#define FFDIM    512
#define TEM2     64
#define NTILES   (EDGES / TEM2)
#define GRID_E   148
#define TNN      128
#define NTH      512
#define SCALE_F  30.0f
#define LN_EPS   1e-5f

#define SA2 272

// edge smem layout (bytes) — X2/X3 now have private buffers (3-sync pipeline)
#define EW1B_OFF 0
#define EW2_OFF  (128 * SA2)                 // 34816
#define EW3_OFF  (2 * 128 * SA2)             // 69632
#define EPS_OFF  (3 * 128 * SA2)             // 104448: PS fp32 64x132 (33792 B)
#define EXB_OFF  (EPS_OFF + 64 * 132 * 4)    // 138240: XB (hE bf16)
#define EX2_OFF  (EXB_OFF + 64 * SA2)        // 155648: X2
#define EX3_OFF  (EX2_OFF + 64 * SA2)        // 173056: X3
#define EDGE_SMEM (EX3_OFF + 64 * SA2)       // 190464

// precompute kernel smem layout
#define PWA_OFF  0
#define PWC_OFF  (128 * SA2)
#define PX_OFF   (2 * 128 * SA2)
#define PST_OFF  (3 * 128 * SA2)
#define PRE_SMEM (PST_OFF + 128 * 132 * 4)

// node kernel smem layout
#define HS_STRIDE 132
#define HS_BYTES  (TNN * HS_STRIDE * 4)
#define NX_OFF    HS_BYTES
#define NH_OFF    (NX_OFF + 128 * SA2)
#define NW_OFF    (NH_OFF + 128 * SA2)
#define NODE_SMEM (NW_OFF + 128 * SA2)

__device__ float g_nsum[(size_t)NNODES * HDIM];
__device__ float g_cnt[NNODES];
__device__ float g_pre_s[(size_t)NNODES * HDIM];
__device__ float g_pre_d[(size_t)NNODES * HDIM];

__device__ __forceinline__ float gelu_exact(float x) {
    return 0.5f * x * (1.0f + erff(x * 0.70710678118654752440f));
}
__device__ __forceinline__ uint32_t smem_u32(const void* p) {
    uint32_t a;
    asm("{ .reg .u64 t; cvta.to.shared.u64 t, %1; cvt.u32.u64 %0, t; }" : "=r"(a) : "l"(p));
    return a;
}
__device__ __forceinline__ void ldsm4(uint32_t r[4], uint32_t addr) {
    asm volatile("ldmatrix.sync.aligned.m8n8.x4.shared.b16 {%0,%1,%2,%3}, [%4];"
                 : "=r"(r[0]), "=r"(r[1]), "=r"(r[2]), "=r"(r[3]) : "r"(addr));
}
__device__ __forceinline__ void mma_bf16(float c[4], const uint32_t a[4],
                                         uint32_t b0, uint32_t b1) {
    asm volatile("mma.sync.aligned.m16n8k16.row.col.f32.bf16.bf16.f32 "
                 "{%0,%1,%2,%3}, {%4,%5,%6,%7}, {%8,%9}, {%0,%1,%2,%3};"
                 : "+f"(c[0]), "+f"(c[1]), "+f"(c[2]), "+f"(c[3])
                 : "r"(a[0]), "r"(a[1]), "r"(a[2]), "r"(a[3]), "r"(b0), "r"(b1));
}
__device__ __forceinline__ void st_bf16x4(char* dst, float4 v) {
    __nv_bfloat162 h0 = __floats2bfloat162_rn(v.x, v.y);
    __nv_bfloat162 h1 = __floats2bfloat162_rn(v.z, v.w);
    uint32_t u0, u1;
    memcpy(&u0, &h0, 4); memcpy(&u1, &h1, 4);
    *(uint2*)dst = make_uint2(u0, u1);
}

// generic warp tile: M = 32 (2 x m16), N = NP*16
template <int KTOT, int SA, int SW, int NP>
__device__ __forceinline__ void mma_tile(const char* A, const char* W,
                                         float (&acc)[2][2 * NP][4],
                                         int wm, int wn, int lane) {
    int row_off = (lane & 7) + ((lane >> 3) & 1) * 8;
    int col_off = (lane >> 4) * 8;
#pragma unroll
    for (int k0 = 0; k0 < KTOT; k0 += 16) {
        uint32_t a[2][4];
#pragma unroll
        for (int mi = 0; mi < 2; mi++)
            ldsm4(a[mi], smem_u32(A + (wm * 32 + mi * 16 + row_off) * SA
                                     + (k0 + col_off) * 2));
        uint32_t b[NP][4];
#pragma unroll
        for (int np = 0; np < NP; np++)
            ldsm4(b[np], smem_u32(W + (wn * 16 * NP + np * 16 + row_off) * SW
                                     + (k0 + col_off) * 2));
#pragma unroll
        for (int mi = 0; mi < 2; mi++)
#pragma unroll
            for (int np = 0; np < NP; np++) {
                mma_bf16(acc[mi][2 * np],     a[mi], b[np][0], b[np][2]);
                mma_bf16(acc[mi][2 * np + 1], a[mi], b[np][1], b[np][3]);
            }
    }
}
template <int NP>
__device__ __forceinline__ void init_bias(float (&acc)[2][2 * NP][4],
                                          const float* sb, int wn, int q) {
#pragma unroll
    for (int ni = 0; ni < 2 * NP; ni++) {
        int c = wn * 16 * NP + ni * 8 + q * 2;
        float v0 = sb[c], v1 = sb[c + 1];
#pragma unroll
        for (int mi = 0; mi < 2; mi++) {
            acc[mi][ni][0] = v0; acc[mi][ni][1] = v1;
            acc[mi][ni][2] = v0; acc[mi][ni][3] = v1;
        }
    }
}
template <int NP>
__device__ __forceinline__ void epi_gelu(char* X, float (&acc)[2][2 * NP][4],
                                         int wm, int wn, int g, int q) {
#pragma unroll
    for (int mi = 0; mi < 2; mi++) {
        int r0 = wm * 32 + mi * 16 + g;
#pragma unroll
        for (int ni = 0; ni < 2 * NP; ni++) {
            int c = wn * 16 * NP + ni * 8 + q * 2;
            __nv_bfloat162 h0 = __floats2bfloat162_rn(gelu_exact(acc[mi][ni][0]),
                                                      gelu_exact(acc[mi][ni][1]));
            __nv_bfloat162 h1 = __floats2bfloat162_rn(gelu_exact(acc[mi][ni][2]),
                                                      gelu_exact(acc[mi][ni][3]));
            uint32_t u0, u1;
            memcpy(&u0, &h0, 4); memcpy(&u1, &h1, 4);
            *(uint32_t*)(X + r0 * SA2 + c * 2) = u0;
            *(uint32_t*)(X + (r0 + 8) * SA2 + c * 2) = u1;
        }
    }
}
template <int NP>
__device__ __forceinline__ void frag_to_f32(float* ST, float (&acc)[2][2 * NP][4],
                                            int wm, int wn, int g, int q) {
#pragma unroll
    for (int mi = 0; mi < 2; mi++) {
        int r0 = wm * 32 + mi * 16 + g;
#pragma unroll
        for (int ni = 0; ni < 2 * NP; ni++) {
            int c = wn * 16 * NP + ni * 8 + q * 2;
            *(float2*)(ST + r0 * 132 + c)       = make_float2(acc[mi][ni][0], acc[mi][ni][1]);
            *(float2*)(ST + (r0 + 8) * 132 + c) = make_float2(acc[mi][ni][2], acc[mi][ni][3]);
        }
    }
}

// ============================================================================
// Precompute kernel: pre_s = hV @ W1a^T + b1 ; pre_d = hV @ W1c^T
// ============================================================================
__global__ __launch_bounds__(NTH, 1) void pre_kernel(
    const float* __restrict__ hV, const float* __restrict__ W1,
    const float* __restrict__ b1)
{
    extern __shared__ char smem[];
    char*  Wa = smem + PWA_OFF;
    char*  Wc = smem + PWC_OFF;
    char*  X  = smem + PX_OFF;
    float* ST = (float*)(smem + PST_OFF);

    __shared__ float s_b1[HDIM];

    int tid = threadIdx.x;
    int wid = tid >> 5;
    int lane = tid & 31;
    int wm = wid & 3, wn = wid >> 2;
    int g = lane >> 2, q = lane & 3;
    int n0 = blockIdx.x * TNN;

    if (tid < HDIM) s_b1[tid] = b1[tid];

#pragma unroll 4
    for (int t = 0; t < 8; t++) {
        int idx = tid + t * NTH;
        int n = idx >> 5, c4 = idx & 31;
        st_bf16x4(Wa + n * SA2 + c4 * 8, *(const float4*)(W1 + (size_t)n * K1 + c4 * 4));
        st_bf16x4(Wc + n * SA2 + c4 * 8, *(const float4*)(W1 + (size_t)n * K1 + 256 + c4 * 4));
        int gn = n0 + n;
        float4 v = make_float4(0.f, 0.f, 0.f, 0.f);
        if (gn < NNODES) v = *(const float4*)(hV + (size_t)gn * HDIM + c4 * 4);
        st_bf16x4(X + n * SA2 + c4 * 8, v);
    }
    __syncthreads();

    float acc_s[2][4][4], acc_d[2][4][4];
    init_bias<2>(acc_s, s_b1, wn, q);
    mma_tile<HDIM, SA2, SA2, 2>(X, Wa, acc_s, wm, wn, lane);
#pragma unroll
    for (int mi = 0; mi < 2; mi++)
#pragma unroll
        for (int ni = 0; ni < 4; ni++)
#pragma unroll
            for (int k = 0; k < 4; k++) acc_d[mi][ni][k] = 0.f;
    mma_tile<HDIM, SA2, SA2, 2>(X, Wc, acc_d, wm, wn, lane);

    frag_to_f32<2>(ST, acc_s, wm, wn, g, q);
    __syncthreads();
#pragma unroll 4
    for (int t = 0; t < 32; t++) {
        int idx = tid + t * NTH;
        int n = idx >> 7, o = idx & 127;
        int gn = n0 + n;
        if (gn < NNODES) g_pre_s[(size_t)gn * HDIM + o] = ST[n * 132 + o];
    }
    __syncthreads();
    frag_to_f32<2>(ST, acc_d, wm, wn, g, q);
    __syncthreads();
#pragma unroll 4
    for (int t = 0; t < 32; t++) {
        int idx = tid + t * NTH;
        int n = idx >> 7, o = idx & 127;
        int gn = n0 + n;
        if (gn < NNODES) g_pre_d[(size_t)gn * HDIM + o] = ST[n * 132 + o];
    }
}

// prefetch one tile: pre_s[src]+pre_d[dst] pairs and hE, into registers
__device__ __forceinline__ void prefetch_tile(
    size_t e0, const float* __restrict__ hE,
    const int* __restrict__ src, const int* __restrict__ dst,
    int tid, float4 (&ps)[4], float4 (&pd)[4], float4 (&he)[4])
{
#pragma unroll
    for (int t = 0; t < 4; t++) {
        int idx = tid + t * NTH;
        int e = idx >> 5, c4 = idx & 31;
        int s = src[e0 + e];
        int d = dst[e0 + e];
        ps[t] = *(const float4*)(g_pre_s + (size_t)s * HDIM + c4 * 4);
        pd[t] = *(const float4*)(g_pre_d + (size_t)d * HDIM + c4 * 4);
        he[t] = *(const float4*)(hE + (e0 + e) * HDIM + c4 * 4);
    }
}

// ============================================================================
// Edge kernel: factored layer-1, persistent weights, 3-sync pipeline
// ============================================================================
__global__ __launch_bounds__(NTH, 1) void edge_kernel_p(
    const float* __restrict__ hE,
    const int* __restrict__ src, const int* __restrict__ dst,
    const float* __restrict__ W1, const float* __restrict__ b2w,
    const float* __restrict__ W2, const float* __restrict__ W3,
    const float* __restrict__ b3w)
{
    extern __shared__ char smem[];
    char*  W1s = smem + EW1B_OFF;     // W1b = cols 128..255
    char*  W2s = smem + EW2_OFF;
    char*  W3s = smem + EW3_OFF;
    float* PS  = (float*)(smem + EPS_OFF);
    char*  XB  = smem + EXB_OFF;      // hE bf16
    char*  X2  = smem + EX2_OFF;
    char*  X3  = smem + EX3_OFF;

    __shared__ int   sidx[2][TEM2];
    __shared__ float s_b2[HDIM], s_b3[HDIM];

    int tid = threadIdx.x;
    int wid = tid >> 5;
    int lane = tid & 31;
    int wm = wid & 1, wn = wid >> 1;     // 2M x 8N, NP=1
    int g = lane >> 2, q = lane & 3;

    if (tid < HDIM) { s_b2[tid] = b2w[tid]; s_b3[tid] = b3w[tid]; }
    // persistent weight staging
#pragma unroll 4
    for (int t = 0; t < 8; t++) {
        int idx = tid + t * NTH;
        int n = idx >> 5, c4 = idx & 31;
        st_bf16x4(W1s + n * SA2 + c4 * 8, *(const float4*)(W1 + (size_t)n * K1 + 128 + c4 * 4));
        st_bf16x4(W2s + n * SA2 + c4 * 8, *(const float4*)(W2 + (size_t)n * HDIM + c4 * 4));
        st_bf16x4(W3s + n * SA2 + c4 * 8, *(const float4*)(W3 + (size_t)n * HDIM + c4 * 4));
    }

    int tile0 = blockIdx.x;
    float4 ps[4], pd[4], he[4];
    {
        size_t e0 = (size_t)tile0 * TEM2;
        if (tid < TEM2) sidx[0][tid] = src[e0 + tid];
        prefetch_tile(e0, hE, src, dst, tid, ps, pd, he);
    }
    __syncthreads();

    int p = 0;
    for (int tile = tile0; tile < NTILES; tile += GRID_E, p ^= 1) {
        const int* si = sidx[p];

        // ---- phase A: gather stores (pure STS from prefetched registers) ----
#pragma unroll
        for (int t = 0; t < 4; t++) {
            int idx = tid + t * NTH;
            int e = idx >> 5, c4 = idx & 31;
            st_bf16x4(XB + e * SA2 + c4 * 8, he[t]);
            *(float4*)(PS + e * 132 + c4 * 4) =
                make_float4(ps[t].x + pd[t].x, ps[t].y + pd[t].y,
                            ps[t].z + pd[t].z, ps[t].w + pd[t].w);
        }
        __syncthreads();                              // S1: gather -> mma1

        // ---- next tile prefetch (hidden under MMA phases) ----
        int tnext = tile + GRID_E;
        if (tnext < NTILES) {
            size_t e0n = (size_t)tnext * TEM2;
            if (tid < TEM2) sidx[p ^ 1][tid] = src[e0n + tid];
            prefetch_tile(e0n, hE, src, dst, tid, ps, pd, he);
        }

        float acc[2][2][4];

        // ---- layer 1: acc init from PS, K=128 over hE ----
#pragma unroll
        for (int mi = 0; mi < 2; mi++) {
            int r0 = wm * 32 + mi * 16 + g;
#pragma unroll
            for (int ni = 0; ni < 2; ni++) {
                int c = wn * 16 + ni * 8 + q * 2;
                float2 v0 = *(float2*)(PS + r0 * 132 + c);
                float2 v1 = *(float2*)(PS + (r0 + 8) * 132 + c);
                acc[mi][ni][0] = v0.x; acc[mi][ni][1] = v0.y;
                acc[mi][ni][2] = v1.x; acc[mi][ni][3] = v1.y;
            }
        }
        mma_tile<HDIM, SA2, SA2, 1>(XB, W1s, acc, wm, wn, lane);
        epi_gelu<1>(X2, acc, wm, wn, g, q);           // X2 private buffer
        __syncthreads();                              // S2: epi1 -> mma2

        // ---- layer 2 ----
        init_bias<1>(acc, s_b2, wn, q);
        mma_tile<HDIM, SA2, SA2, 1>(X2, W2s, acc, wm, wn, lane);
        epi_gelu<1>(X3, acc, wm, wn, g, q);           // X3 private buffer
        __syncthreads();                              // S3: epi2 -> mma3

        // ---- layer 3 ----
        init_bias<1>(acc, s_b3, wn, q);
        mma_tile<HDIM, SA2, SA2, 1>(X3, W3s, acc, wm, wn, lane);

        // ---- direct scatter (float2 vector atomics); no trailing sync ----
#pragma unroll
        for (int mi = 0; mi < 2; mi++) {
            int r0 = wm * 32 + mi * 16 + g;
            float* row0 = &g_nsum[(size_t)si[r0] * HDIM];
            float* row1 = &g_nsum[(size_t)si[r0 + 8] * HDIM];
#pragma unroll
            for (int ni = 0; ni < 2; ni++) {
                int c = wn * 16 + ni * 8 + q * 2;
                atomicAdd((float2*)(row0 + c), make_float2(acc[mi][ni][0], acc[mi][ni][1]));
                atomicAdd((float2*)(row1 + c), make_float2(acc[mi][ni][2], acc[mi][ni][3]));
            }
        }
        if (tid < TEM2) atomicAdd(&g_cnt[si[tid]], 1.0f);
        // next phase A writes XB/PS, whose last readers finished before S2;
        // X3 reads (mma3) are separated from next epi2 by next-tile S1+S2.
    }
}

// ============================================================================
// Node kernel (unchanged)
// ============================================================================
__global__ __launch_bounds__(NTH, 1) void node_kernel_mma(
    const float* __restrict__ hV,
    const float* __restrict__ ln1g, const float* __restrict__ ln1b,
    const float* __restrict__ ln2g, const float* __restrict__ ln2b,
    const float* __restrict__ Win,  const float* __restrict__ bin,
    const float* __restrict__ Wout, const float* __restrict__ bout,
    float* __restrict__ out)
{
    extern __shared__ char smem[];
    float* hs = (float*)smem;
    char*  X  = smem + NX_OFF;
    char*  Hb = smem + NH_OFF;
    char*  Wb = smem + NW_OFF;

    __shared__ float s_bout[HDIM];

    int tid = threadIdx.x;
    int wid = tid >> 5;
    int lane = tid & 31;
    int wm = wid & 3, wn = wid >> 2;
    int g = lane >> 2, q = lane & 3;
    int n0 = blockIdx.x * TNN;

    if (tid < HDIM) s_bout[tid] = bout[tid];

#pragma unroll 4
    for (int t = 0; t < 32; t++) {
        int idx = tid + t * NTH;
        int n = idx >> 7, o = idx & 127;
        int gn = n0 + n;
        float v = 0.0f;
        if (gn < NNODES) {
            float c = fmaxf(g_cnt[gn], 1.0f);
            v = hV[(size_t)gn * HDIM + o] + g_nsum[(size_t)gn * HDIM + o] / (c * SCALE_F);
        }
        hs[n * HS_STRIDE + o] = v;
    }
    __syncthreads();

    {
        int n = tid >> 2, q4 = tid & 3;
        float s = 0.0f, ss = 0.0f;
#pragma unroll
        for (int jj = 0; jj < 32; jj++) {
            float v = hs[n * HS_STRIDE + q4 * 32 + jj];
            s += v; ss += v * v;
        }
#pragma unroll
        for (int m = 1; m < 4; m <<= 1) {
            s  += __shfl_xor_sync(0xffffffffu, s,  m);
            ss += __shfl_xor_sync(0xffffffffu, ss, m);
        }
        float mu   = s * (1.0f / 128.0f);
        float var  = ss * (1.0f / 128.0f) - mu * mu;
        float rstd = rsqrtf(var + LN_EPS);
#pragma unroll
        for (int jj = 0; jj < 32; jj += 2) {
            int o = q4 * 32 + jj;
            float v0 = (hs[n * HS_STRIDE + o]     - mu) * rstd * ln1g[o]     + ln1b[o];
            float v1 = (hs[n * HS_STRIDE + o + 1] - mu) * rstd * ln1g[o + 1] + ln1b[o + 1];
            hs[n * HS_STRIDE + o]     = v0;
            hs[n * HS_STRIDE + o + 1] = v1;
            __nv_bfloat162 hh = __floats2bfloat162_rn(v0, v1);
            uint32_t u; memcpy(&u, &hh, 4);
            *(uint32_t*)(X + n * SA2 + o * 2) = u;
        }
    }

    float dh[2][4][4];
    init_bias<2>(dh, s_bout, wn, q);

    for (int nb = 0; nb < 4; nb++) {
        __syncthreads();
#pragma unroll 4
        for (int t = 0; t < 8; t++) {
            int idx = tid + t * NTH;
            int n = idx >> 5, c4 = idx & 31;
            st_bf16x4(Wb + n * SA2 + c4 * 8,
                      *(const float4*)(Win + (size_t)(nb * 128 + n) * HDIM + c4 * 4));
        }
        __syncthreads();

        float acc[2][4][4];
        init_bias<2>(acc, bin + nb * 128, wn, q);
        mma_tile<HDIM, SA2, SA2, 2>(X, Wb, acc, wm, wn, lane);
        __syncthreads();
        epi_gelu<2>(Hb, acc, wm, wn, g, q);

#pragma unroll 4
        for (int t = 0; t < 8; t++) {
            int idx = tid + t * NTH;
            int n = idx >> 5, c4 = idx & 31;
            st_bf16x4(Wb + n * SA2 + c4 * 8,
                      *(const float4*)(Wout + (size_t)n * FFDIM + nb * 128 + c4 * 4));
        }
        __syncthreads();

        mma_tile<HDIM, SA2, SA2, 2>(Hb, Wb, dh, wm, wn, lane);
    }
    __syncthreads();

    float* zs = (float*)X;
#pragma unroll
    for (int mi = 0; mi < 2; mi++) {
        int r0 = wm * 32 + mi * 16 + g;
#pragma unroll
        for (int ni = 0; ni < 4; ni++) {
            int c = wn * 32 + ni * 8 + q * 2;
            zs[r0 * 132 + c]           = dh[mi][ni][0] + hs[r0 * HS_STRIDE + c];
            zs[r0 * 132 + c + 1]       = dh[mi][ni][1] + hs[r0 * HS_STRIDE + c + 1];
            zs[(r0 + 8) * 132 + c]     = dh[mi][ni][2] + hs[(r0 + 8) * HS_STRIDE + c];
            zs[(r0 + 8) * 132 + c + 1] = dh[mi][ni][3] + hs[(r0 + 8) * HS_STRIDE + c + 1];
        }
    }
    __syncthreads();

    {
        int n = tid >> 2, q4 = tid & 3;
        float s = 0.0f, ss = 0.0f;
#pragma unroll
        for (int jj = 0; jj < 32; jj++) {
            float v = zs[n * 132 + q4 * 32 + jj];
            s += v; ss += v * v;
        }
#pragma unroll
        for (int m = 1; m < 4; m <<= 1) {
            s  += __shfl_xor_sync(0xffffffffu, s,  m);
            ss += __shfl_xor_sync(0xffffffffu, ss, m);
        }
        float mu   = s * (1.0f / 128.0f);
        float var  = ss * (1.0f / 128.0f) - mu * mu;
        float rstd = rsqrtf(var + LN_EPS);
        int gn = n0 + n;
        if (gn < NNODES) {
#pragma unroll
            for (int jj = 0; jj < 32; jj++) {
                int o = q4 * 32 + jj;
                float v = zs[n * 132 + o];
                out[(size_t)gn * HDIM + o] = (v - mu) * rstd * ln2g[o] + ln2b[o];
            }
        }
    }
}

// ============================================================================
// Launch
// ============================================================================
extern "C" void kernel_launch(void* const* d_in, const int* in_sizes, int n_in,
                              void* d_out, int out_size)
{
    const float* hV   = (const float*)d_in[0];
    const float* hE   = (const float*)d_in[1];
    const int*   src  = (const int*)  d_in[2];
    const int*   dst  = (const int*)  d_in[4];
    const float* W1   = (const float*)d_in[5];
    const float* b1   = (const float*)d_in[6];
    const float* W2   = (const float*)d_in[7];
    const float* b2   = (const float*)d_in[8];
    const float* W3   = (const float*)d_in[9];
    const float* b3   = (const float*)d_in[10];
    const float* ln1g = (const float*)d_in[11];
    const float* ln1b = (const float*)d_in[12];
    const float* ln2g = (const float*)d_in[13];
    const float* ln2b = (const float*)d_in[14];
    const float* Win  = (const float*)d_in[15];
    const float* bin  = (const float*)d_in[16];
    const float* Wout = (const float*)d_in[17];
    const float* bout = (const float*)d_in[18];
    float* out = (float*)d_out;

    cudaFuncSetAttribute(pre_kernel, cudaFuncAttributeMaxDynamicSharedMemorySize, PRE_SMEM);
    cudaFuncSetAttribute(edge_kernel_p, cudaFuncAttributeMaxDynamicSharedMemorySize, EDGE_SMEM);
    cudaFuncSetAttribute(node_kernel_mma, cudaFuncAttributeMaxDynamicSharedMemorySize, NODE_SMEM);

    void* nsum_p = nullptr;
    void* cnt_p  = nullptr;
    cudaGetSymbolAddress(&nsum_p, g_nsum);
    cudaGetSymbolAddress(&cnt_p,  g_cnt);
    cudaMemsetAsync(nsum_p, 0, sizeof(float) * (size_t)NNODES * HDIM);
    cudaMemsetAsync(cnt_p,  0, sizeof(float) * NNODES);

    int nblk = (NNODES + TNN - 1) / TNN;
    pre_kernel<<<nblk, NTH, PRE_SMEM>>>(hV, W1, b1);
    edge_kernel_p<<<GRID_E, NTH, EDGE_SMEM>>>(hE, src, dst, W1, b2, W2, W3, b3);
    node_kernel_mma<<<nblk, NTH, NODE_SMEM>>>(
        hV, ln1g, ln1b, ln2g, ln2b, Win, bin, Wout, bout, out);
}

// round 16
// speedup vs baseline: 1.9267x; 1.1844x over previous
#include <cuda_runtime.h>
#include <cuda_bf16.h>
#include <math.h>
#include <stdint.h>
#include <string.h>

#define EDGES    800000
#define NNODES   50000
#define HDIM     128
#define K1       384
#define FFDIM    512
#define TEM2     64
#define NTILES   (EDGES / TEM2)
#define GRID_E   148
#define TNN      128
#define NTH      512
#define SCALE_F  30.0f
#define LN_EPS   1e-5f

#define SA2 272

// edge smem layout (bytes) — private X2/X3 buffers (3-sync pipeline)
#define EW1B_OFF 0
#define EW2_OFF  (128 * SA2)                 // 34816
#define EW3_OFF  (2 * 128 * SA2)             // 69632
#define EPS_OFF  (3 * 128 * SA2)             // 104448: PS fp32 64x132
#define EXB_OFF  (EPS_OFF + 64 * 132 * 4)    // 138240: XB (hE bf16)
#define EX2_OFF  (EXB_OFF + 64 * SA2)        // 155648: X2
#define EX3_OFF  (EX2_OFF + 64 * SA2)        // 173056: X3
#define EDGE_SMEM (EX3_OFF + 64 * SA2)       // 190464

// precompute kernel smem layout
#define PWA_OFF  0
#define PWC_OFF  (128 * SA2)
#define PX_OFF   (2 * 128 * SA2)
#define PST_OFF  (3 * 128 * SA2)
#define PRE_SMEM (PST_OFF + 128 * 132 * 4)

// node kernel smem layout
#define HS_STRIDE 132
#define HS_BYTES  (TNN * HS_STRIDE * 4)
#define NX_OFF    HS_BYTES
#define NH_OFF    (NX_OFF + 128 * SA2)
#define NW_OFF    (NH_OFF + 128 * SA2)
#define NODE_SMEM (NW_OFF + 128 * SA2)

__device__ float g_nsum[(size_t)NNODES * HDIM];
__device__ float g_cnt[NNODES];
__device__ float g_pre_s[(size_t)NNODES * HDIM];
__device__ float g_pre_d[(size_t)NNODES * HDIM];

__device__ __forceinline__ float gelu_exact(float x) {
    return 0.5f * x * (1.0f + erff(x * 0.70710678118654752440f));
}
// fast tanh-GELU (MUFU.TANH) — edge path only; |err| vs exact <= ~3e-4,
// and edge messages are diluted /30 before the residual.
__device__ __forceinline__ float gelu_fast(float x) {
    float x3 = x * x * x;
    float y = 0.7978845608028654f * fmaf(0.044715f, x3, x);
    float t;
    asm("tanh.approx.f32 %0, %1;" : "=f"(t) : "f"(y));
    return 0.5f * x * (1.0f + t);
}
__device__ __forceinline__ uint32_t smem_u32(const void* p) {
    uint32_t a;
    asm("{ .reg .u64 t; cvta.to.shared.u64 t, %1; cvt.u32.u64 %0, t; }" : "=r"(a) : "l"(p));
    return a;
}
__device__ __forceinline__ void ldsm4(uint32_t r[4], uint32_t addr) {
    asm volatile("ldmatrix.sync.aligned.m8n8.x4.shared.b16 {%0,%1,%2,%3}, [%4];"
                 : "=r"(r[0]), "=r"(r[1]), "=r"(r[2]), "=r"(r[3]) : "r"(addr));
}
__device__ __forceinline__ void mma_bf16(float c[4], const uint32_t a[4],
                                         uint32_t b0, uint32_t b1) {
    asm volatile("mma.sync.aligned.m16n8k16.row.col.f32.bf16.bf16.f32 "
                 "{%0,%1,%2,%3}, {%4,%5,%6,%7}, {%8,%9}, {%0,%1,%2,%3};"
                 : "+f"(c[0]), "+f"(c[1]), "+f"(c[2]), "+f"(c[3])
                 : "r"(a[0]), "r"(a[1]), "r"(a[2]), "r"(a[3]), "r"(b0), "r"(b1));
}
__device__ __forceinline__ void st_bf16x4(char* dst, float4 v) {
    __nv_bfloat162 h0 = __floats2bfloat162_rn(v.x, v.y);
    __nv_bfloat162 h1 = __floats2bfloat162_rn(v.z, v.w);
    uint32_t u0, u1;
    memcpy(&u0, &h0, 4); memcpy(&u1, &h1, 4);
    *(uint2*)dst = make_uint2(u0, u1);
}

// generic warp tile: M = 32 (2 x m16), N = NP*16
template <int KTOT, int SA, int SW, int NP>
__device__ __forceinline__ void mma_tile(const char* A, const char* W,
                                         float (&acc)[2][2 * NP][4],
                                         int wm, int wn, int lane) {
    int row_off = (lane & 7) + ((lane >> 3) & 1) * 8;
    int col_off = (lane >> 4) * 8;
#pragma unroll
    for (int k0 = 0; k0 < KTOT; k0 += 16) {
        uint32_t a[2][4];
#pragma unroll
        for (int mi = 0; mi < 2; mi++)
            ldsm4(a[mi], smem_u32(A + (wm * 32 + mi * 16 + row_off) * SA
                                     + (k0 + col_off) * 2));
        uint32_t b[NP][4];
#pragma unroll
        for (int np = 0; np < NP; np++)
            ldsm4(b[np], smem_u32(W + (wn * 16 * NP + np * 16 + row_off) * SW
                                     + (k0 + col_off) * 2));
#pragma unroll
        for (int mi = 0; mi < 2; mi++)
#pragma unroll
            for (int np = 0; np < NP; np++) {
                mma_bf16(acc[mi][2 * np],     a[mi], b[np][0], b[np][2]);
                mma_bf16(acc[mi][2 * np + 1], a[mi], b[np][1], b[np][3]);
            }
    }
}
template <int NP>
__device__ __forceinline__ void init_bias(float (&acc)[2][2 * NP][4],
                                          const float* sb, int wn, int q) {
#pragma unroll
    for (int ni = 0; ni < 2 * NP; ni++) {
        int c = wn * 16 * NP + ni * 8 + q * 2;
        float v0 = sb[c], v1 = sb[c + 1];
#pragma unroll
        for (int mi = 0; mi < 2; mi++) {
            acc[mi][ni][0] = v0; acc[mi][ni][1] = v1;
            acc[mi][ni][2] = v0; acc[mi][ni][3] = v1;
        }
    }
}
// exact-erf epilogue (node kernel)
template <int NP>
__device__ __forceinline__ void epi_gelu(char* X, float (&acc)[2][2 * NP][4],
                                         int wm, int wn, int g, int q) {
#pragma unroll
    for (int mi = 0; mi < 2; mi++) {
        int r0 = wm * 32 + mi * 16 + g;
#pragma unroll
        for (int ni = 0; ni < 2 * NP; ni++) {
            int c = wn * 16 * NP + ni * 8 + q * 2;
            __nv_bfloat162 h0 = __floats2bfloat162_rn(gelu_exact(acc[mi][ni][0]),
                                                      gelu_exact(acc[mi][ni][1]));
            __nv_bfloat162 h1 = __floats2bfloat162_rn(gelu_exact(acc[mi][ni][2]),
                                                      gelu_exact(acc[mi][ni][3]));
            uint32_t u0, u1;
            memcpy(&u0, &h0, 4); memcpy(&u1, &h1, 4);
            *(uint32_t*)(X + r0 * SA2 + c * 2) = u0;
            *(uint32_t*)(X + (r0 + 8) * SA2 + c * 2) = u1;
        }
    }
}
// fast tanh-GELU epilogue (edge kernel)
template <int NP>
__device__ __forceinline__ void epi_gelu_f(char* X, float (&acc)[2][2 * NP][4],
                                           int wm, int wn, int g, int q) {
#pragma unroll
    for (int mi = 0; mi < 2; mi++) {
        int r0 = wm * 32 + mi * 16 + g;
#pragma unroll
        for (int ni = 0; ni < 2 * NP; ni++) {
            int c = wn * 16 * NP + ni * 8 + q * 2;
            __nv_bfloat162 h0 = __floats2bfloat162_rn(gelu_fast(acc[mi][ni][0]),
                                                      gelu_fast(acc[mi][ni][1]));
            __nv_bfloat162 h1 = __floats2bfloat162_rn(gelu_fast(acc[mi][ni][2]),
                                                      gelu_fast(acc[mi][ni][3]));
            uint32_t u0, u1;
            memcpy(&u0, &h0, 4); memcpy(&u1, &h1, 4);
            *(uint32_t*)(X + r0 * SA2 + c * 2) = u0;
            *(uint32_t*)(X + (r0 + 8) * SA2 + c * 2) = u1;
        }
    }
}
template <int NP>
__device__ __forceinline__ void frag_to_f32(float* ST, float (&acc)[2][2 * NP][4],
                                            int wm, int wn, int g, int q) {
#pragma unroll
    for (int mi = 0; mi < 2; mi++) {
        int r0 = wm * 32 + mi * 16 + g;
#pragma unroll
        for (int ni = 0; ni < 2 * NP; ni++) {
            int c = wn * 16 * NP + ni * 8 + q * 2;
            *(float2*)(ST + r0 * 132 + c)       = make_float2(acc[mi][ni][0], acc[mi][ni][1]);
            *(float2*)(ST + (r0 + 8) * 132 + c) = make_float2(acc[mi][ni][2], acc[mi][ni][3]);
        }
    }
}

// ============================================================================
// Precompute kernel: pre_s = hV @ W1a^T + b1 ; pre_d = hV @ W1c^T
// ============================================================================
__global__ __launch_bounds__(NTH, 1) void pre_kernel(
    const float* __restrict__ hV, const float* __restrict__ W1,
    const float* __restrict__ b1)
{
    extern __shared__ char smem[];
    char*  Wa = smem + PWA_OFF;
    char*  Wc = smem + PWC_OFF;
    char*  X  = smem + PX_OFF;
    float* ST = (float*)(smem + PST_OFF);

    __shared__ float s_b1[HDIM];

    int tid = threadIdx.x;
    int wid = tid >> 5;
    int lane = tid & 31;
    int wm = wid & 3, wn = wid >> 2;
    int g = lane >> 2, q = lane & 3;
    int n0 = blockIdx.x * TNN;

    if (tid < HDIM) s_b1[tid] = b1[tid];

#pragma unroll 4
    for (int t = 0; t < 8; t++) {
        int idx = tid + t * NTH;
        int n = idx >> 5, c4 = idx & 31;
        st_bf16x4(Wa + n * SA2 + c4 * 8, *(const float4*)(W1 + (size_t)n * K1 + c4 * 4));
        st_bf16x4(Wc + n * SA2 + c4 * 8, *(const float4*)(W1 + (size_t)n * K1 + 256 + c4 * 4));
        int gn = n0 + n;
        float4 v = make_float4(0.f, 0.f, 0.f, 0.f);
        if (gn < NNODES) v = *(const float4*)(hV + (size_t)gn * HDIM + c4 * 4);
        st_bf16x4(X + n * SA2 + c4 * 8, v);
    }
    __syncthreads();

    float acc_s[2][4][4], acc_d[2][4][4];
    init_bias<2>(acc_s, s_b1, wn, q);
    mma_tile<HDIM, SA2, SA2, 2>(X, Wa, acc_s, wm, wn, lane);
#pragma unroll
    for (int mi = 0; mi < 2; mi++)
#pragma unroll
        for (int ni = 0; ni < 4; ni++)
#pragma unroll
            for (int k = 0; k < 4; k++) acc_d[mi][ni][k] = 0.f;
    mma_tile<HDIM, SA2, SA2, 2>(X, Wc, acc_d, wm, wn, lane);

    frag_to_f32<2>(ST, acc_s, wm, wn, g, q);
    __syncthreads();
#pragma unroll 4
    for (int t = 0; t < 32; t++) {
        int idx = tid + t * NTH;
        int n = idx >> 7, o = idx & 127;
        int gn = n0 + n;
        if (gn < NNODES) g_pre_s[(size_t)gn * HDIM + o] = ST[n * 132 + o];
    }
    __syncthreads();
    frag_to_f32<2>(ST, acc_d, wm, wn, g, q);
    __syncthreads();
#pragma unroll 4
    for (int t = 0; t < 32; t++) {
        int idx = tid + t * NTH;
        int n = idx >> 7, o = idx & 127;
        int gn = n0 + n;
        if (gn < NNODES) g_pre_d[(size_t)gn * HDIM + o] = ST[n * 132 + o];
    }
}

// prefetch one tile: pre_s[src]+pre_d[dst] pairs and hE, into registers
__device__ __forceinline__ void prefetch_tile(
    size_t e0, const float* __restrict__ hE,
    const int* __restrict__ src, const int* __restrict__ dst,
    int tid, float4 (&ps)[4], float4 (&pd)[4], float4 (&he)[4])
{
#pragma unroll
    for (int t = 0; t < 4; t++) {
        int idx = tid + t * NTH;
        int e = idx >> 5, c4 = idx & 31;
        int s = src[e0 + e];
        int d = dst[e0 + e];
        ps[t] = *(const float4*)(g_pre_s + (size_t)s * HDIM + c4 * 4);
        pd[t] = *(const float4*)(g_pre_d + (size_t)d * HDIM + c4 * 4);
        he[t] = *(const float4*)(hE + (e0 + e) * HDIM + c4 * 4);
    }
}

// ============================================================================
// Edge kernel: factored layer-1, persistent weights, 3-sync pipeline,
// fast tanh-GELU epilogues
// ============================================================================
__global__ __launch_bounds__(NTH, 1) void edge_kernel_p(
    const float* __restrict__ hE,
    const int* __restrict__ src, const int* __restrict__ dst,
    const float* __restrict__ W1, const float* __restrict__ b2w,
    const float* __restrict__ W2, const float* __restrict__ W3,
    const float* __restrict__ b3w)
{
    extern __shared__ char smem[];
    char*  W1s = smem + EW1B_OFF;     // W1b = cols 128..255
    char*  W2s = smem + EW2_OFF;
    char*  W3s = smem + EW3_OFF;
    float* PS  = (float*)(smem + EPS_OFF);
    char*  XB  = smem + EXB_OFF;      // hE bf16
    char*  X2  = smem + EX2_OFF;
    char*  X3  = smem + EX3_OFF;

    __shared__ int   sidx[2][TEM2];
    __shared__ float s_b2[HDIM], s_b3[HDIM];

    int tid = threadIdx.x;
    int wid = tid >> 5;
    int lane = tid & 31;
    int wm = wid & 1, wn = wid >> 1;     // 2M x 8N, NP=1
    int g = lane >> 2, q = lane & 3;

    if (tid < HDIM) { s_b2[tid] = b2w[tid]; s_b3[tid] = b3w[tid]; }
    // persistent weight staging
#pragma unroll 4
    for (int t = 0; t < 8; t++) {
        int idx = tid + t * NTH;
        int n = idx >> 5, c4 = idx & 31;
        st_bf16x4(W1s + n * SA2 + c4 * 8, *(const float4*)(W1 + (size_t)n * K1 + 128 + c4 * 4));
        st_bf16x4(W2s + n * SA2 + c4 * 8, *(const float4*)(W2 + (size_t)n * HDIM + c4 * 4));
        st_bf16x4(W3s + n * SA2 + c4 * 8, *(const float4*)(W3 + (size_t)n * HDIM + c4 * 4));
    }

    int tile0 = blockIdx.x;
    float4 ps[4], pd[4], he[4];
    {
        size_t e0 = (size_t)tile0 * TEM2;
        if (tid < TEM2) sidx[0][tid] = src[e0 + tid];
        prefetch_tile(e0, hE, src, dst, tid, ps, pd, he);
    }
    __syncthreads();

    int p = 0;
    for (int tile = tile0; tile < NTILES; tile += GRID_E, p ^= 1) {
        const int* si = sidx[p];

        // ---- phase A: gather stores (pure STS from prefetched registers) ----
#pragma unroll
        for (int t = 0; t < 4; t++) {
            int idx = tid + t * NTH;
            int e = idx >> 5, c4 = idx & 31;
            st_bf16x4(XB + e * SA2 + c4 * 8, he[t]);
            *(float4*)(PS + e * 132 + c4 * 4) =
                make_float4(ps[t].x + pd[t].x, ps[t].y + pd[t].y,
                            ps[t].z + pd[t].z, ps[t].w + pd[t].w);
        }
        __syncthreads();                              // S1: gather -> mma1

        // ---- next tile prefetch (hidden under MMA phases) ----
        int tnext = tile + GRID_E;
        if (tnext < NTILES) {
            size_t e0n = (size_t)tnext * TEM2;
            if (tid < TEM2) sidx[p ^ 1][tid] = src[e0n + tid];
            prefetch_tile(e0n, hE, src, dst, tid, ps, pd, he);
        }

        float acc[2][2][4];

        // ---- layer 1: acc init from PS, K=128 over hE ----
#pragma unroll
        for (int mi = 0; mi < 2; mi++) {
            int r0 = wm * 32 + mi * 16 + g;
#pragma unroll
            for (int ni = 0; ni < 2; ni++) {
                int c = wn * 16 + ni * 8 + q * 2;
                float2 v0 = *(float2*)(PS + r0 * 132 + c);
                float2 v1 = *(float2*)(PS + (r0 + 8) * 132 + c);
                acc[mi][ni][0] = v0.x; acc[mi][ni][1] = v0.y;
                acc[mi][ni][2] = v1.x; acc[mi][ni][3] = v1.y;
            }
        }
        mma_tile<HDIM, SA2, SA2, 1>(XB, W1s, acc, wm, wn, lane);
        epi_gelu_f<1>(X2, acc, wm, wn, g, q);         // fast GELU
        __syncthreads();                              // S2: epi1 -> mma2

        // ---- layer 2 ----
        init_bias<1>(acc, s_b2, wn, q);
        mma_tile<HDIM, SA2, SA2, 1>(X2, W2s, acc, wm, wn, lane);
        epi_gelu_f<1>(X3, acc, wm, wn, g, q);         // fast GELU
        __syncthreads();                              // S3: epi2 -> mma3

        // ---- layer 3 ----
        init_bias<1>(acc, s_b3, wn, q);
        mma_tile<HDIM, SA2, SA2, 1>(X3, W3s, acc, wm, wn, lane);

        // ---- direct scatter (float2 vector atomics); no trailing sync ----
#pragma unroll
        for (int mi = 0; mi < 2; mi++) {
            int r0 = wm * 32 + mi * 16 + g;
            float* row0 = &g_nsum[(size_t)si[r0] * HDIM];
            float* row1 = &g_nsum[(size_t)si[r0 + 8] * HDIM];
#pragma unroll
            for (int ni = 0; ni < 2; ni++) {
                int c = wn * 16 + ni * 8 + q * 2;
                atomicAdd((float2*)(row0 + c), make_float2(acc[mi][ni][0], acc[mi][ni][1]));
                atomicAdd((float2*)(row1 + c), make_float2(acc[mi][ni][2], acc[mi][ni][3]));
            }
        }
        if (tid < TEM2) atomicAdd(&g_cnt[si[tid]], 1.0f);
    }
}

// ============================================================================
// Node kernel (unchanged — exact erf GELU)
// ============================================================================
__global__ __launch_bounds__(NTH, 1) void node_kernel_mma(
    const float* __restrict__ hV,
    const float* __restrict__ ln1g, const float* __restrict__ ln1b,
    const float* __restrict__ ln2g, const float* __restrict__ ln2b,
    const float* __restrict__ Win,  const float* __restrict__ bin,
    const float* __restrict__ Wout, const float* __restrict__ bout,
    float* __restrict__ out)
{
    extern __shared__ char smem[];
    float* hs = (float*)smem;
    char*  X  = smem + NX_OFF;
    char*  Hb = smem + NH_OFF;
    char*  Wb = smem + NW_OFF;

    __shared__ float s_bout[HDIM];

    int tid = threadIdx.x;
    int wid = tid >> 5;
    int lane = tid & 31;
    int wm = wid & 3, wn = wid >> 2;
    int g = lane >> 2, q = lane & 3;
    int n0 = blockIdx.x * TNN;

    if (tid < HDIM) s_bout[tid] = bout[tid];

#pragma unroll 4
    for (int t = 0; t < 32; t++) {
        int idx = tid + t * NTH;
        int n = idx >> 7, o = idx & 127;
        int gn = n0 + n;
        float v = 0.0f;
        if (gn < NNODES) {
            float c = fmaxf(g_cnt[gn], 1.0f);
            v = hV[(size_t)gn * HDIM + o] + g_nsum[(size_t)gn * HDIM + o] / (c * SCALE_F);
        }
        hs[n * HS_STRIDE + o] = v;
    }
    __syncthreads();

    {
        int n = tid >> 2, q4 = tid & 3;
        float s = 0.0f, ss = 0.0f;
#pragma unroll
        for (int jj = 0; jj < 32; jj++) {
            float v = hs[n * HS_STRIDE + q4 * 32 + jj];
            s += v; ss += v * v;
        }
#pragma unroll
        for (int m = 1; m < 4; m <<= 1) {
            s  += __shfl_xor_sync(0xffffffffu, s,  m);
            ss += __shfl_xor_sync(0xffffffffu, ss, m);
        }
        float mu   = s * (1.0f / 128.0f);
        float var  = ss * (1.0f / 128.0f) - mu * mu;
        float rstd = rsqrtf(var + LN_EPS);
#pragma unroll
        for (int jj = 0; jj < 32; jj += 2) {
            int o = q4 * 32 + jj;
            float v0 = (hs[n * HS_STRIDE + o]     - mu) * rstd * ln1g[o]     + ln1b[o];
            float v1 = (hs[n * HS_STRIDE + o + 1] - mu) * rstd * ln1g[o + 1] + ln1b[o + 1];
            hs[n * HS_STRIDE + o]     = v0;
            hs[n * HS_STRIDE + o + 1] = v1;
            __nv_bfloat162 hh = __floats2bfloat162_rn(v0, v1);
            uint32_t u; memcpy(&u, &hh, 4);
            *(uint32_t*)(X + n * SA2 + o * 2) = u;
        }
    }

    float dh[2][4][4];
    init_bias<2>(dh, s_bout, wn, q);

    for (int nb = 0; nb < 4; nb++) {
        __syncthreads();
#pragma unroll 4
        for (int t = 0; t < 8; t++) {
            int idx = tid + t * NTH;
            int n = idx >> 5, c4 = idx & 31;
            st_bf16x4(Wb + n * SA2 + c4 * 8,
                      *(const float4*)(Win + (size_t)(nb * 128 + n) * HDIM + c4 * 4));
        }
        __syncthreads();

        float acc[2][4][4];
        init_bias<2>(acc, bin + nb * 128, wn, q);
        mma_tile<HDIM, SA2, SA2, 2>(X, Wb, acc, wm, wn, lane);
        __syncthreads();
        epi_gelu<2>(Hb, acc, wm, wn, g, q);

#pragma unroll 4
        for (int t = 0; t < 8; t++) {
            int idx = tid + t * NTH;
            int n = idx >> 5, c4 = idx & 31;
            st_bf16x4(Wb + n * SA2 + c4 * 8,
                      *(const float4*)(Wout + (size_t)n * FFDIM + nb * 128 + c4 * 4));
        }
        __syncthreads();

        mma_tile<HDIM, SA2, SA2, 2>(Hb, Wb, dh, wm, wn, lane);
    }
    __syncthreads();

    float* zs = (float*)X;
#pragma unroll
    for (int mi = 0; mi < 2; mi++) {
        int r0 = wm * 32 + mi * 16 + g;
#pragma unroll
        for (int ni = 0; ni < 4; ni++) {
            int c = wn * 32 + ni * 8 + q * 2;
            zs[r0 * 132 + c]           = dh[mi][ni][0] + hs[r0 * HS_STRIDE + c];
            zs[r0 * 132 + c + 1]       = dh[mi][ni][1] + hs[r0 * HS_STRIDE + c + 1];
            zs[(r0 + 8) * 132 + c]     = dh[mi][ni][2] + hs[(r0 + 8) * HS_STRIDE + c];
            zs[(r0 + 8) * 132 + c + 1] = dh[mi][ni][3] + hs[(r0 + 8) * HS_STRIDE + c + 1];
        }
    }
    __syncthreads();

    {
        int n = tid >> 2, q4 = tid & 3;
        float s = 0.0f, ss = 0.0f;
#pragma unroll
        for (int jj = 0; jj < 32; jj++) {
            float v = zs[n * 132 + q4 * 32 + jj];
            s += v; ss += v * v;
        }
#pragma unroll
        for (int m = 1; m < 4; m <<= 1) {
            s  += __shfl_xor_sync(0xffffffffu, s,  m);
            ss += __shfl_xor_sync(0xffffffffu, ss, m);
        }
        float mu   = s * (1.0f / 128.0f);
        float var  = ss * (1.0f / 128.0f) - mu * mu;
        float rstd = rsqrtf(var + LN_EPS);
        int gn = n0 + n;
        if (gn < NNODES) {
#pragma unroll
            for (int jj = 0; jj < 32; jj++) {
                int o = q4 * 32 + jj;
                float v = zs[n * 132 + o];
                out[(size_t)gn * HDIM + o] = (v - mu) * rstd * ln2g[o] + ln2b[o];
            }
        }
    }
}

// ============================================================================
// Launch
// ============================================================================
extern "C" void kernel_launch(void* const* d_in, const int* in_sizes, int n_in,
                              void* d_out, int out_size)
{
    const float* hV   = (const float*)d_in[0];
    const float* hE   = (const float*)d_in[1];
    const int*   src  = (const int*)  d_in[2];
    const int*   dst  = (const int*)  d_in[4];
    const float* W1   = (const float*)d_in[5];
    const float* b1   = (const float*)d_in[6];
    const float* W2   = (const float*)d_in[7];
    const float* b2   = (const float*)d_in[8];
    const float* W3   = (const float*)d_in[9];
    const float* b3   = (const float*)d_in[10];
    const float* ln1g = (const float*)d_in[11];
    const float* ln1b = (const float*)d_in[12];
    const float* ln2g = (const float*)d_in[13];
    const float* ln2b = (const float*)d_in[14];
    const float* Win  = (const float*)d_in[15];
    const float* bin  = (const float*)d_in[16];
    const float* Wout = (const float*)d_in[17];
    const float* bout = (const float*)d_in[18];
    float* out = (float*)d_out;

    cudaFuncSetAttribute(pre_kernel, cudaFuncAttributeMaxDynamicSharedMemorySize, PRE_SMEM);
    cudaFuncSetAttribute(edge_kernel_p, cudaFuncAttributeMaxDynamicSharedMemorySize, EDGE_SMEM);
    cudaFuncSetAttribute(node_kernel_mma, cudaFuncAttributeMaxDynamicSharedMemorySize, NODE_SMEM);

    void* nsum_p = nullptr;
    void* cnt_p  = nullptr;
    cudaGetSymbolAddress(&nsum_p, g_nsum);
    cudaGetSymbolAddress(&cnt_p,  g_cnt);
    cudaMemsetAsync(nsum_p, 0, sizeof(float) * (size_t)NNODES * HDIM);
    cudaMemsetAsync(cnt_p,  0, sizeof(float) * NNODES);

    int nblk = (NNODES + TNN - 1) / TNN;
    pre_kernel<<<nblk, NTH, PRE_SMEM>>>(hV, W1, b1);
    edge_kernel_p<<<GRID_E, NTH, EDGE_SMEM>>>(hE, src, dst, W1, b2, W2, W3, b3);
    node_kernel_mma<<<nblk, NTH, NODE_SMEM>>>(
        hV, ln1g, ln1b, ln2g, ln2b, Win, bin, Wout, bout, out);
}